// round 3
// baseline (speedup 1.0000x reference)
#include <cuda_runtime.h>

#define HID  64
#define FEAT 9
#define TT   36
#define BLK  128

// ---- shared layout (float offsets) ----
#define OFF_WG     0         // [64][82][4] interleaved gate weights = 20992
#define OFF_B4     20992     // [64][4] combined LSTM bias = 256
#define OFF_WGHT   21248     // [9][64] Wgh TRANSPOSED = 576
#define OFF_BGH    21824     // 64
#define OFF_WHT    21888     // [64][16] Whist TRANSPOSED (cols 9..15 zero) = 1024
#define OFF_BHIST  22912     // 12 (9 + zero pad)
#define OFF_WGXD   22924     // 12
#define OFF_BGX    22936     // 12
#define OFF_WFEAT  22948     // 84
#define OFF_BFEAT  23032     // 12
#define OFF_WCOMB  23044     // 164
#define OFF_BCOMB  23208     // 12
#define OFF_INV    23220     // 36
#define OFF_H      23256     // [128][68]
#define OFF_C      (OFF_H + BLK*68)
#define SMEM_FLOATS (OFF_C + BLK*68)
#define SMEM_BYTES  (SMEM_FLOATS * 4)

__device__ float g_denom[TT];
__device__ float g_partials[1024];

typedef unsigned long long u64;

__device__ __forceinline__ void fma2(u64& acc, u64 a, u64 b) {
    asm("fma.rn.f32x2 %0, %1, %2, %0;" : "+l"(acc) : "l"(a), "l"(b));
}
__device__ __forceinline__ u64 pack2(float lo, float hi) {
    u64 r; asm("mov.b64 %0, {%1, %2};" : "=l"(r) : "f"(lo), "f"(hi)); return r;
}
__device__ __forceinline__ u64 dup2(float v) { return pack2(v, v); }
__device__ __forceinline__ float2 unpack2(u64 v) {
    float2 r; asm("mov.b64 {%0, %1}, %2;" : "=f"(r.x), "=f"(r.y) : "l"(v)); return r;
}
__device__ __forceinline__ float fsigmoid(float x) {
    return __fdividef(1.0f, 1.0f + __expf(-x));
}
__device__ __forceinline__ float ftanhx(float x) {
    float e = __expf(2.0f * x);
    return 1.0f - __fdividef(2.0f, e + 1.0f);
}

// ---- denom: zero bins, then coalesced accumulate (exact-integer atomics) ----
__global__ void zero_denom_kernel() {
    if (threadIdx.x < TT) g_denom[threadIdx.x] = 0.0f;
}

__global__ void denom_kernel(const float* __restrict__ masks, int B) {
    __shared__ float bins[TT];
    if (threadIdx.x < TT) bins[threadIdx.x] = 0.0f;
    __syncthreads();
    int idx = blockIdx.x * blockDim.x + threadIdx.x;  // one per (b, t)
    if (idx < B * TT) {
        int t = idx % TT;
        const float* p = masks + (size_t)idx * FEAT;  // [b][t][.] contiguous
        float sv = 0.0f;
        #pragma unroll
        for (int f = 0; f < FEAT; f++) sv += p[f];
        atomicAdd(&bins[t], sv);   // all addends exact integers -> deterministic
    }
    __syncthreads();
    if (threadIdx.x < TT) atomicAdd(&g_denom[threadIdx.x], bins[threadIdx.x]);
}

__global__ void __launch_bounds__(BLK)
rits_main_kernel(const float* __restrict__ values,
                 const float* __restrict__ masks,
                 const float* __restrict__ deltas,
                 const float* __restrict__ Wgh, const float* __restrict__ bgh,
                 const float* __restrict__ Wgx, const float* __restrict__ bgx,
                 const float* __restrict__ Whist, const float* __restrict__ bhist,
                 const float* __restrict__ Wfeat, const float* __restrict__ bfeat,
                 const float* __restrict__ Wcomb, const float* __restrict__ bcomb,
                 const float* __restrict__ Wih, const float* __restrict__ Whh,
                 const float* __restrict__ bih, const float* __restrict__ bhh,
                 float* __restrict__ out, int B) {
    extern __shared__ float s[];
    const int tid = threadIdx.x;
    const int b = blockIdx.x * BLK + tid;

    // ---- stage weights into shared (all >BLK regions strided!) ----
    for (int idx = tid; idx < 64 * 82 * 4; idx += BLK) {
        int g = idx & 3;
        int jk = idx >> 2;
        int j = jk / 82, k = jk - j * 82;
        int row = g * HID + j;
        s[OFF_WG + idx] = (k < 18) ? Wih[row * 18 + k] : Whh[row * HID + (k - 18)];
    }
    for (int idx = tid; idx < 256; idx += BLK) {
        int g = idx & 3, j = idx >> 2;
        s[OFF_B4 + idx] = bih[g * HID + j] + bhh[g * HID + j];
    }
    for (int idx = tid; idx < 576; idx += BLK) {       // Wgh transposed [f][j]
        int f = idx >> 6, j = idx & 63;
        s[OFF_WGHT + idx] = Wgh[j * FEAT + f];
    }
    for (int idx = tid; idx < 1024; idx += BLK) {      // Whist transposed [k][f16]
        int k = idx >> 4, f = idx & 15;
        s[OFF_WHT + idx] = (f < FEAT) ? Whist[f * HID + k] : 0.0f;
    }
    for (int idx = tid; idx < 164; idx += BLK)
        s[OFF_WCOMB + idx] = (idx < 162) ? Wcomb[idx] : 0.0f;
    if (tid < 64) s[OFF_BGH + tid] = bgh[tid];
    if (tid < 12) {
        s[OFF_BHIST + tid] = (tid < 9) ? bhist[tid] : 0.0f;
        s[OFF_WGXD + tid] = (tid < 9) ? Wgx[tid * FEAT + tid] : 0.0f;
        s[OFF_BGX + tid] = (tid < 9) ? bgx[tid] : 0.0f;
        s[OFF_BFEAT + tid] = (tid < 9) ? bfeat[tid] : 0.0f;
        s[OFF_BCOMB + tid] = (tid < 9) ? bcomb[tid] : 0.0f;
    }
    if (tid < 84) {
        int f = tid / 9, f2 = tid - f * 9;
        s[OFF_WFEAT + tid] = (tid < 81 && f != f2) ? Wfeat[tid] : 0.0f;
    }
    if (tid < TT) s[OFF_INV + tid] = 1.0f / (g_denom[tid] + 1e-5f);

    float* myh = s + OFF_H + tid * 68;
    float* myc = s + OFF_C + tid * 68;
    #pragma unroll
    for (int k = 0; k < 64; k++) { myh[k] = 0.0f; myc[k] = 0.0f; }
    __syncthreads();

    float loss = 0.0f;
    if (b < B) {
        const float* xb = values + (size_t)b * (TT * FEAT);
        const float* mb = masks + (size_t)b * (TT * FEAT);
        const float* db = deltas + (size_t)b * (TT * FEAT);
        float* ob = out + 1 + (size_t)b * (TT * FEAT);

        for (int t = 0; t < TT; t++) {
            float x[9], m[9], d[9];
            #pragma unroll
            for (int f = 0; f < 9; f++) {
                x[f] = xb[t * 9 + f];
                m[f] = mb[t * 9 + f];
                d[f] = db[t * 9 + f];
            }

            // ---- decay pre-activation a[j] (paired over j), f32x2 ----
            u64 accD[32];
            {
                const ulonglong2* bg = (const ulonglong2*)(s + OFF_BGH);
                #pragma unroll
                for (int q = 0; q < 16; q++) {
                    ulonglong2 v = bg[q];
                    accD[2 * q] = v.x; accD[2 * q + 1] = v.y;
                }
                #pragma unroll
                for (int f = 0; f < 9; f++) {
                    u64 dd = dup2(d[f]);
                    const ulonglong2* wr = (const ulonglong2*)(s + OFF_WGHT + f * 64);
                    #pragma unroll
                    for (int q = 0; q < 16; q++) {
                        ulonglong2 w = wr[q];
                        fma2(accD[2 * q], dd, w.x);
                        fma2(accD[2 * q + 1], dd, w.y);
                    }
                }
            }

            // ---- apply decay to h, build duplicated pairs hdup[j]=(h,h) ----
            u64 hdup[64];
            #pragma unroll
            for (int q = 0; q < 16; q++) {
                float4 hv = *(const float4*)(myh + 4 * q);
                float2 a0 = unpack2(accD[2 * q]);
                float2 a1 = unpack2(accD[2 * q + 1]);
                hdup[4 * q]     = dup2(hv.x * __expf(-fmaxf(a0.x, 0.0f)));
                hdup[4 * q + 1] = dup2(hv.y * __expf(-fmaxf(a0.y, 0.0f)));
                hdup[4 * q + 2] = dup2(hv.z * __expf(-fmaxf(a1.x, 0.0f)));
                hdup[4 * q + 3] = dup2(hv.w * __expf(-fmaxf(a1.y, 0.0f)));
            }

            // ---- history regression x_h (feature-paired), f32x2 ----
            float xh[9];
            {
                const u64* bh = (const u64*)(s + OFF_BHIST);
                u64 a01 = bh[0], a23 = bh[1], a45 = bh[2], a67 = bh[3], a8p = bh[4];
                #pragma unroll
                for (int k = 0; k < 64; k++) {
                    const ulonglong2* wr = (const ulonglong2*)(s + OFF_WHT + k * 16);
                    ulonglong2 w0 = wr[0];
                    ulonglong2 w1 = wr[1];
                    u64 w8 = ((const u64*)(s + OFF_WHT + k * 16))[4];
                    u64 hk = hdup[k];
                    fma2(a01, hk, w0.x);
                    fma2(a23, hk, w0.y);
                    fma2(a45, hk, w1.x);
                    fma2(a67, hk, w1.y);
                    fma2(a8p, hk, w8);
                }
                float2 r;
                r = unpack2(a01); xh[0] = r.x; xh[1] = r.y;
                r = unpack2(a23); xh[2] = r.x; xh[3] = r.y;
                r = unpack2(a45); xh[4] = r.x; xh[5] = r.y;
                r = unpack2(a67); xh[6] = r.x; xh[7] = r.y;
                r = unpack2(a8p); xh[8] = r.x;
            }

            float xc[9], gx[9];
            #pragma unroll
            for (int f = 0; f < 9; f++) {
                xc[f] = m[f] * x[f] + (1.0f - m[f]) * xh[f];
                gx[f] = __expf(-fmaxf(fmaf(d[f], s[OFF_WGXD + f], s[OFF_BGX + f]), 0.0f));
            }

            u64 inpd[18];
            float lsum = 0.0f;
            #pragma unroll
            for (int f = 0; f < 9; f++) {
                const float* wf = s + OFF_WFEAT + f * 9;
                float zh = s[OFF_BFEAT + f];
                #pragma unroll
                for (int k = 0; k < 9; k++) zh = fmaf(xc[k], wf[k], zh);
                const float* wc = s + OFF_WCOMB + f * 18;
                float al = s[OFF_BCOMB + f];
                #pragma unroll
                for (int k = 0; k < 9; k++) al = fmaf(gx[k], wc[k], al);
                #pragma unroll
                for (int k = 0; k < 9; k++) al = fmaf(m[k], wc[9 + k], al);
                float ch = al * zh + (1.0f - al) * xh[f];
                lsum += m[f] * (fabsf(x[f] - xh[f]) + fabsf(x[f] - zh) + fabsf(x[f] - ch));
                float c_c = m[f] * x[f] + (1.0f - m[f]) * ch;
                ob[t * 9 + f] = c_c;
                inpd[f] = dup2(c_c);
                inpd[9 + f] = dup2(m[f]);
            }
            loss = fmaf(lsum, s[OFF_INV + t], loss);

            // ---- LSTM gates: (i,f) and (g,o) as f32x2 pair accumulators ----
            #pragma unroll 1
            for (int j = 0; j < 64; j++) {
                ulonglong2 bb = *(const ulonglong2*)(s + OFF_B4 + j * 4);
                u64 aIF = bb.x, aGO = bb.y;
                const ulonglong2* wj = (const ulonglong2*)(s + OFF_WG + j * 328);
                #pragma unroll
                for (int k = 0; k < 18; k++) {
                    ulonglong2 w = wj[k];
                    fma2(aIF, inpd[k], w.x);
                    fma2(aGO, inpd[k], w.y);
                }
                #pragma unroll
                for (int k = 0; k < 64; k++) {
                    ulonglong2 w = wj[18 + k];
                    fma2(aIF, hdup[k], w.x);
                    fma2(aGO, hdup[k], w.y);
                }
                float2 vif = unpack2(aIF);
                float2 vgo = unpack2(aGO);
                float cn = fsigmoid(vif.y) * myc[j] + fsigmoid(vif.x) * ftanhx(vgo.x);
                myc[j] = cn;
                myh[j] = fsigmoid(vgo.y) * ftanhx(cn);
            }
        }
    }

    // deterministic block reduction of loss
    #pragma unroll
    for (int o = 16; o; o >>= 1) loss += __shfl_down_sync(~0u, loss, o);
    __shared__ float red[4];
    if ((tid & 31) == 0) red[tid >> 5] = loss;
    __syncthreads();
    if (tid == 0) g_partials[blockIdx.x] = (red[0] + red[1]) + (red[2] + red[3]);
}

__global__ void finalize_kernel(float* __restrict__ out, int nblocks) {
    float sv = 0.0f;
    for (int i = threadIdx.x; i < nblocks; i += 256) sv += g_partials[i];
    __shared__ float red[8];
    #pragma unroll
    for (int o = 16; o; o >>= 1) sv += __shfl_down_sync(~0u, sv, o);
    if ((threadIdx.x & 31) == 0) red[threadIdx.x >> 5] = sv;
    __syncthreads();
    if (threadIdx.x < 8) {
        sv = red[threadIdx.x];
        #pragma unroll
        for (int o = 4; o; o >>= 1) sv += __shfl_down_sync(0xff, sv, o);
        if (threadIdx.x == 0) out[0] = sv * (1.0f / (float)TT);
    }
}

extern "C" void kernel_launch(void* const* d_in, const int* in_sizes, int n_in,
                              void* d_out, int out_size) {
    const float* values = (const float*)d_in[0];
    const float* masks  = (const float*)d_in[1];
    const float* deltas = (const float*)d_in[2];
    const float* Wgh   = (const float*)d_in[3];
    const float* bgh   = (const float*)d_in[4];
    const float* Wgx   = (const float*)d_in[5];
    const float* bgx   = (const float*)d_in[6];
    const float* Whist = (const float*)d_in[7];
    const float* bhist = (const float*)d_in[8];
    const float* Wfeat = (const float*)d_in[9];
    const float* bfeat = (const float*)d_in[10];
    const float* Wcomb = (const float*)d_in[11];
    const float* bcomb = (const float*)d_in[12];
    const float* Wih   = (const float*)d_in[13];
    const float* Whh   = (const float*)d_in[14];
    const float* bih   = (const float*)d_in[15];
    const float* bhh   = (const float*)d_in[16];
    float* out = (float*)d_out;

    int B = in_sizes[0] / (TT * FEAT);
    int nb = (B + BLK - 1) / BLK;

    cudaFuncSetAttribute(rits_main_kernel,
                         cudaFuncAttributeMaxDynamicSharedMemorySize, SMEM_BYTES);

    zero_denom_kernel<<<1, 64>>>();
    denom_kernel<<<(B * TT + 255) / 256, 256>>>(masks, B);
    rits_main_kernel<<<nb, BLK, SMEM_BYTES>>>(
        values, masks, deltas, Wgh, bgh, Wgx, bgx, Whist, bhist,
        Wfeat, bfeat, Wcomb, bcomb, Wih, Whh, bih, bhh, out, B);
    finalize_kernel<<<1, 256>>>(out, nb);
}

// round 5
// speedup vs baseline: 2.5819x; 2.5819x over previous
#include <cuda_runtime.h>

#define HID  64
#define FEAT 9
#define TT   36
#define BLK  128

// ---- shared layout (float offsets) ----
#define OFF_WG     0                  // [64][82][4] interleaved gates = 20992
#define OFF_B4     20992              // [64][4] combined bias = 256
#define OFF_WGH    21248              // [64][9] = 576
#define OFF_BGH    21824              // 64
#define OFF_WHIST  21888              // [9][64] = 576
#define OFF_BHIST  22464              // 9 (+3 pad)
#define OFF_WGXD   22476              // 9 (+3)
#define OFF_BGX    22488              // 9 (+3)
#define OFF_WFEAT  22500              // 81 (+3)
#define OFF_BFEAT  22584              // 9 (+3)
#define OFF_WCOMB  22596              // 162 (+2)
#define OFF_BCOMB  22760              // 9 (+3)
#define OFF_INV    22772              // 36
#define OFF_H      22808              // [128][68]
#define OFF_C      (OFF_H + BLK*68)
#define SMEM_FLOATS (OFF_C + BLK*68)
#define SMEM_BYTES  (SMEM_FLOATS * 4)

__device__ float g_denom[TT];
__device__ float g_partials[1024];

__device__ __forceinline__ float fsigmoid(float x) {
    return __fdividef(1.0f, 1.0f + __expf(-x));
}
__device__ __forceinline__ float ftanhx(float x) {
    float e = __expf(2.0f * x);
    return 1.0f - __fdividef(2.0f, e + 1.0f);
}

// ---- denom: zero bins, then coalesced accumulate (exact-integer atomics) ----
__global__ void zero_denom_kernel() {
    if (threadIdx.x < TT) g_denom[threadIdx.x] = 0.0f;
}

__global__ void denom_kernel(const float* __restrict__ masks, int B) {
    __shared__ float bins[TT];
    if (threadIdx.x < TT) bins[threadIdx.x] = 0.0f;
    __syncthreads();
    int idx = blockIdx.x * blockDim.x + threadIdx.x;  // one per (b, t) row
    if (idx < B * TT) {
        int t = idx % TT;
        const float* p = masks + (size_t)idx * FEAT;  // [b][t][.] contiguous
        float sv = 0.0f;
        #pragma unroll
        for (int f = 0; f < FEAT; f++) sv += p[f];
        atomicAdd(&bins[t], sv);   // all addends exact integers -> deterministic
    }
    __syncthreads();
    if (threadIdx.x < TT) atomicAdd(&g_denom[threadIdx.x], bins[threadIdx.x]);
}

__global__ void __launch_bounds__(BLK)
rits_main_kernel(const float* __restrict__ values,
                 const float* __restrict__ masks,
                 const float* __restrict__ deltas,
                 const float* __restrict__ Wgh, const float* __restrict__ bgh,
                 const float* __restrict__ Wgx, const float* __restrict__ bgx,
                 const float* __restrict__ Whist, const float* __restrict__ bhist,
                 const float* __restrict__ Wfeat, const float* __restrict__ bfeat,
                 const float* __restrict__ Wcomb, const float* __restrict__ bcomb,
                 const float* __restrict__ Wih, const float* __restrict__ Whh,
                 const float* __restrict__ bih, const float* __restrict__ bhh,
                 float* __restrict__ out, int B) {
    extern __shared__ float s[];
    const int tid = threadIdx.x;
    const int b = blockIdx.x * BLK + tid;

    // ---- stage weights into shared ----
    for (int idx = tid; idx < 64 * 82 * 4; idx += BLK) {
        int g = idx & 3;
        int jk = idx >> 2;
        int j = jk / 82, k = jk - j * 82;
        int row = g * HID + j;
        s[OFF_WG + idx] = (k < 18) ? Wih[row * 18 + k] : Whh[row * HID + (k - 18)];
    }
    for (int idx = tid; idx < 256; idx += BLK) {
        int g = idx & 3, j = idx >> 2;
        s[OFF_B4 + idx] = bih[g * HID + j] + bhh[g * HID + j];
    }
    for (int idx = tid; idx < 576; idx += BLK) {
        s[OFF_WGH + idx] = Wgh[idx];
        s[OFF_WHIST + idx] = Whist[idx];
    }
    // W_comb has 162 elements (> BLK): strided loop
    for (int idx = tid; idx < 162; idx += BLK) s[OFF_WCOMB + idx] = Wcomb[idx];
    if (tid < 64) s[OFF_BGH + tid] = bgh[tid];
    if (tid < 9) {
        s[OFF_BHIST + tid] = bhist[tid];
        s[OFF_WGXD + tid] = Wgx[tid * FEAT + tid];
        s[OFF_BGX + tid] = bgx[tid];
        s[OFF_BFEAT + tid] = bfeat[tid];
        s[OFF_BCOMB + tid] = bcomb[tid];
    }
    if (tid < 81) {
        int f = tid / 9, f2 = tid - f * 9;
        s[OFF_WFEAT + tid] = (f == f2) ? 0.0f : Wfeat[tid];
    }
    if (tid < TT) s[OFF_INV + tid] = 1.0f / (g_denom[tid] + 1e-5f);

    float* myh = s + OFF_H + tid * 68;
    float* myc = s + OFF_C + tid * 68;
    #pragma unroll
    for (int k = 0; k < 68; k++) { myh[k] = 0.0f; myc[k] = 0.0f; }
    __syncthreads();

    float loss = 0.0f;
    if (b < B) {
        const float* xb = values + (size_t)b * (TT * FEAT);
        const float* mb = masks + (size_t)b * (TT * FEAT);
        const float* db = deltas + (size_t)b * (TT * FEAT);
        float* ob = out + 1 + (size_t)b * (TT * FEAT);

        for (int t = 0; t < TT; t++) {
            float x[9], m[9], d[9];
            #pragma unroll
            for (int f = 0; f < 9; f++) {
                x[f] = xb[t * 9 + f];
                m[f] = mb[t * 9 + f];
                d[f] = db[t * 9 + f];
            }

            // gamma_h decay applied to h in shared
            #pragma unroll 4
            for (int j = 0; j < 64; j++) {
                const float* w = s + OFF_WGH + j * 9;
                float a = s[OFF_BGH + j];
                #pragma unroll
                for (int f = 0; f < 9; f++) a = fmaf(d[f], w[f], a);
                myh[j] *= __expf(-fmaxf(a, 0.0f));
            }

            // hoist decayed h to registers (conflict-free LDS.128)
            float hreg[64];
            #pragma unroll
            for (int k = 0; k < 16; k++) {
                float4 v = *(const float4*)(myh + 4 * k);
                hreg[4 * k]     = v.x;
                hreg[4 * k + 1] = v.y;
                hreg[4 * k + 2] = v.z;
                hreg[4 * k + 3] = v.w;
            }

            // history regression x_h = h @ W_hist^T + b
            float xh[9];
            #pragma unroll
            for (int f = 0; f < 9; f++) {
                const float4* w = (const float4*)(s + OFF_WHIST + f * 64);
                float a0 = s[OFF_BHIST + f], a1 = 0.0f, a2 = 0.0f, a3 = 0.0f;
                #pragma unroll
                for (int k = 0; k < 16; k++) {
                    float4 wv = w[k];
                    a0 = fmaf(hreg[4 * k],     wv.x, a0);
                    a1 = fmaf(hreg[4 * k + 1], wv.y, a1);
                    a2 = fmaf(hreg[4 * k + 2], wv.z, a2);
                    a3 = fmaf(hreg[4 * k + 3], wv.w, a3);
                }
                xh[f] = (a0 + a1) + (a2 + a3);
            }

            float xc[9], gx[9];
            #pragma unroll
            for (int f = 0; f < 9; f++) {
                xc[f] = m[f] * x[f] + (1.0f - m[f]) * xh[f];
                gx[f] = __expf(-fmaxf(fmaf(d[f], s[OFF_WGXD + f], s[OFF_BGX + f]), 0.0f));
            }

            float inp[18];
            float lsum = 0.0f;
            #pragma unroll
            for (int f = 0; f < 9; f++) {
                const float* wf = s + OFF_WFEAT + f * 9;
                float zh = s[OFF_BFEAT + f];
                #pragma unroll
                for (int k = 0; k < 9; k++) zh = fmaf(xc[k], wf[k], zh);
                const float* wc = s + OFF_WCOMB + f * 18;
                float al = s[OFF_BCOMB + f];
                #pragma unroll
                for (int k = 0; k < 9; k++) al = fmaf(gx[k], wc[k], al);
                #pragma unroll
                for (int k = 0; k < 9; k++) al = fmaf(m[k], wc[9 + k], al);
                float ch = al * zh + (1.0f - al) * xh[f];
                lsum += m[f] * (fabsf(x[f] - xh[f]) + fabsf(x[f] - zh) + fabsf(x[f] - ch));
                float c_c = m[f] * x[f] + (1.0f - m[f]) * ch;
                ob[t * 9 + f] = c_c;
                inp[f] = c_c;
                inp[9 + f] = m[f];
            }
            loss = fmaf(lsum, s[OFF_INV + t], loss);

            // LSTM gates: per unit j, 4 gates via interleaved [j][k][gate] weights
            #pragma unroll 1
            for (int j = 0; j < 64; j++) {
                const float4* wj = (const float4*)(s + OFF_WG + j * 328);
                float4 bb = *(const float4*)(s + OFF_B4 + j * 4);
                float ai = bb.x, af = bb.y, ag = bb.z, ao = bb.w;
                #pragma unroll
                for (int k = 0; k < 18; k++) {
                    float4 w = wj[k];
                    ai = fmaf(inp[k], w.x, ai);
                    af = fmaf(inp[k], w.y, af);
                    ag = fmaf(inp[k], w.z, ag);
                    ao = fmaf(inp[k], w.w, ao);
                }
                #pragma unroll
                for (int k = 0; k < 64; k++) {
                    float4 w = wj[18 + k];
                    ai = fmaf(hreg[k], w.x, ai);
                    af = fmaf(hreg[k], w.y, af);
                    ag = fmaf(hreg[k], w.z, ag);
                    ao = fmaf(hreg[k], w.w, ao);
                }
                float cn = fsigmoid(af) * myc[j] + fsigmoid(ai) * ftanhx(ag);
                myc[j] = cn;
                myh[j] = fsigmoid(ao) * ftanhx(cn);
            }
        }
    }

    // deterministic block reduction of loss
    #pragma unroll
    for (int o = 16; o; o >>= 1) loss += __shfl_down_sync(~0u, loss, o);
    __shared__ float red[4];
    if ((tid & 31) == 0) red[tid >> 5] = loss;
    __syncthreads();
    if (tid == 0) g_partials[blockIdx.x] = (red[0] + red[1]) + (red[2] + red[3]);
}

__global__ void finalize_kernel(float* __restrict__ out, int nblocks) {
    float sv = 0.0f;
    for (int i = threadIdx.x; i < nblocks; i += 256) sv += g_partials[i];
    __shared__ float red[8];
    #pragma unroll
    for (int o = 16; o; o >>= 1) sv += __shfl_down_sync(~0u, sv, o);
    if ((threadIdx.x & 31) == 0) red[threadIdx.x >> 5] = sv;
    __syncthreads();
    if (threadIdx.x < 8) {
        sv = red[threadIdx.x];
        #pragma unroll
        for (int o = 4; o; o >>= 1) sv += __shfl_down_sync(0xff, sv, o);
        if (threadIdx.x == 0) out[0] = sv * (1.0f / (float)TT);
    }
}

extern "C" void kernel_launch(void* const* d_in, const int* in_sizes, int n_in,
                              void* d_out, int out_size) {
    const float* values = (const float*)d_in[0];
    const float* masks  = (const float*)d_in[1];
    const float* deltas = (const float*)d_in[2];
    const float* Wgh   = (const float*)d_in[3];
    const float* bgh   = (const float*)d_in[4];
    const float* Wgx   = (const float*)d_in[5];
    const float* bgx   = (const float*)d_in[6];
    const float* Whist = (const float*)d_in[7];
    const float* bhist = (const float*)d_in[8];
    const float* Wfeat = (const float*)d_in[9];
    const float* bfeat = (const float*)d_in[10];
    const float* Wcomb = (const float*)d_in[11];
    const float* bcomb = (const float*)d_in[12];
    const float* Wih   = (const float*)d_in[13];
    const float* Whh   = (const float*)d_in[14];
    const float* bih   = (const float*)d_in[15];
    const float* bhh   = (const float*)d_in[16];
    float* out = (float*)d_out;

    int B = in_sizes[0] / (TT * FEAT);
    int nb = (B + BLK - 1) / BLK;

    cudaFuncSetAttribute(rits_main_kernel,
                         cudaFuncAttributeMaxDynamicSharedMemorySize, SMEM_BYTES);

    zero_denom_kernel<<<1, 64>>>();
    denom_kernel<<<(B * TT + 255) / 256, 256>>>(masks, B);
    rits_main_kernel<<<nb, BLK, SMEM_BYTES>>>(
        values, masks, deltas, Wgh, bgh, Wgx, bgx, Whist, bhist,
        Wfeat, bfeat, Wcomb, bcomb, Wih, Whh, bih, bhh, out, B);
    finalize_kernel<<<1, 256>>>(out, nb);
}

// round 7
// speedup vs baseline: 2.9160x; 1.1294x over previous
#include <cuda_runtime.h>
#include <cstdint>

#define HID  64
#define FEAT 9
#define TT   36
#define BLK  128

// ---- shared layout (float offsets) ----
#define OFF_WG     0         // [64][41 kpair][4 gate][2 parity] = 20992
#define OFF_B2     20992     // [64][4] u64 bias pairs (bias,0) = 512 floats
#define OFF_WGH    21504     // [64][9] = 576
#define OFF_BGH    22080     // 64
#define OFF_WHIST  22144     // [9][64] = 576
#define OFF_BHIST  22720     // 12
#define OFF_WGXD   22732     // 12
#define OFF_BGX    22744     // 12
#define OFF_WFEAT  22756     // 84
#define OFF_BFEAT  22840     // 12
#define OFF_WCOMB  22852     // 164
#define OFF_BCOMB  23016     // 12
#define OFF_INV    23028     // 36
#define OFF_H      23064     // [128][68]  (byte off 92256, 16B aligned)
#define OFF_C      (OFF_H + BLK*68)
#define SMEM_FLOATS (OFF_C + BLK*68)
#define SMEM_BYTES  (SMEM_FLOATS * 4)

__device__ float g_denom[TT];
__device__ float g_partials[1024];

typedef unsigned long long u64;

__device__ __forceinline__ void fma2(u64& acc, u64 a, u64 b) {
    asm("fma.rn.f32x2 %0, %1, %2, %0;" : "+l"(acc) : "l"(a), "l"(b));
}
__device__ __forceinline__ u64 pack2(float lo, float hi) {
    u64 r; asm("mov.b64 %0, {%1, %2};" : "=l"(r) : "f"(lo), "f"(hi)); return r;
}
__device__ __forceinline__ float2 unpack2(u64 v) {
    float2 r; asm("mov.b64 {%0, %1}, %2;" : "=f"(r.x), "=f"(r.y) : "l"(v)); return r;
}
__device__ __forceinline__ float fsigmoid(float x) {
    return __fdividef(1.0f, 1.0f + __expf(-x));
}
__device__ __forceinline__ float ftanhx(float x) {
    float e = __expf(2.0f * x);
    return 1.0f - __fdividef(2.0f, e + 1.0f);
}

// ---- denom: zero bins, then coalesced accumulate (exact-integer atomics) ----
__global__ void zero_denom_kernel() {
    if (threadIdx.x < TT) g_denom[threadIdx.x] = 0.0f;
}
__global__ void denom_kernel(const float* __restrict__ masks, int B) {
    __shared__ float bins[TT];
    if (threadIdx.x < TT) bins[threadIdx.x] = 0.0f;
    __syncthreads();
    int idx = blockIdx.x * blockDim.x + threadIdx.x;
    if (idx < B * TT) {
        int t = idx % TT;
        const float* p = masks + (size_t)idx * FEAT;
        float sv = 0.0f;
        #pragma unroll
        for (int f = 0; f < FEAT; f++) sv += p[f];
        atomicAdd(&bins[t], sv);
    }
    __syncthreads();
    if (threadIdx.x < TT) atomicAdd(&g_denom[threadIdx.x], bins[threadIdx.x]);
}

__global__ void __launch_bounds__(BLK)
rits_main_kernel(const float* __restrict__ values,
                 const float* __restrict__ masks,
                 const float* __restrict__ deltas,
                 const float* __restrict__ Wgh, const float* __restrict__ bgh,
                 const float* __restrict__ Wgx, const float* __restrict__ bgx,
                 const float* __restrict__ Whist, const float* __restrict__ bhist,
                 const float* __restrict__ Wfeat, const float* __restrict__ bfeat,
                 const float* __restrict__ Wcomb, const float* __restrict__ bcomb,
                 const float* __restrict__ Wih, const float* __restrict__ Whh,
                 const float* __restrict__ bih, const float* __restrict__ bhh,
                 float* __restrict__ out, int B) {
    extern __shared__ float s[];
    const int tid = threadIdx.x;
    const int b = blockIdx.x * BLK + tid;

    // ---- stage gate weights: [j][kp][gate][parity], k = 2*kp+parity ----
    for (int idx = tid; idx < 64 * 328; idx += BLK) {
        int j = idx / 328, r = idx - j * 328;
        int kp = r >> 3, g = (r & 7) >> 1, p = r & 1;
        int k = 2 * kp + p;
        int row = g * HID + j;
        s[OFF_WG + idx] = (k < 18) ? Wih[row * 18 + k] : Whh[row * HID + (k - 18)];
    }
    // bias pairs (bias, 0) per [j][gate]
    for (int idx = tid; idx < 256; idx += BLK) {
        int j = idx >> 2, g = idx & 3;
        s[OFF_B2 + idx * 2]     = bih[g * HID + j] + bhh[g * HID + j];
        s[OFF_B2 + idx * 2 + 1] = 0.0f;
    }
    for (int idx = tid; idx < 576; idx += BLK) {
        s[OFF_WGH + idx] = Wgh[idx];
        s[OFF_WHIST + idx] = Whist[idx];
    }
    for (int idx = tid; idx < 164; idx += BLK)
        s[OFF_WCOMB + idx] = (idx < 162) ? Wcomb[idx] : 0.0f;
    if (tid < 64) s[OFF_BGH + tid] = bgh[tid];
    if (tid < 12) {
        s[OFF_BHIST + tid] = (tid < 9) ? bhist[tid] : 0.0f;
        s[OFF_WGXD + tid]  = (tid < 9) ? Wgx[tid * FEAT + tid] : 0.0f;
        s[OFF_BGX + tid]   = (tid < 9) ? bgx[tid] : 0.0f;
        s[OFF_BFEAT + tid] = (tid < 9) ? bfeat[tid] : 0.0f;
        s[OFF_BCOMB + tid] = (tid < 9) ? bcomb[tid] : 0.0f;
    }
    if (tid < 84) {
        int f = tid / 9, f2 = tid - f * 9;
        s[OFF_WFEAT + tid] = (tid < 81 && f != f2) ? Wfeat[tid] : 0.0f;
    }
    if (tid < TT) s[OFF_INV + tid] = 1.0f / (g_denom[tid] + 1e-5f);

    float* myh = s + OFF_H + tid * 68;
    float* myc = s + OFF_C + tid * 68;
    #pragma unroll
    for (int k = 0; k < 68; k++) { myh[k] = 0.0f; myc[k] = 0.0f; }
    __syncthreads();

    float loss = 0.0f;
    if (b < B) {
        const float* xb = values + (size_t)b * (TT * FEAT);
        const float* mb = masks + (size_t)b * (TT * FEAT);
        const float* db = deltas + (size_t)b * (TT * FEAT);
        float* ob = out + 1 + (size_t)b * (TT * FEAT);

        for (int t = 0; t < TT; t++) {
            float x[9], m[9], d[9];
            #pragma unroll
            for (int f = 0; f < 9; f++) {
                x[f] = xb[t * 9 + f];
                m[f] = mb[t * 9 + f];
                d[f] = db[t * 9 + f];
            }

            // ---- decay + hoist: hp[32] = packed pairs of decayed h ----
            u64 hp[32];
            #pragma unroll 4
            for (int q = 0; q < 16; q++) {
                // 4 decay dots for j = 4q .. 4q+3
                const float* w0 = s + OFF_WGH + (4 * q) * 9;
                float a0 = s[OFF_BGH + 4 * q];
                float a1 = s[OFF_BGH + 4 * q + 1];
                float a2 = s[OFF_BGH + 4 * q + 2];
                float a3 = s[OFF_BGH + 4 * q + 3];
                #pragma unroll
                for (int f = 0; f < 9; f++) {
                    float dv = d[f];
                    a0 = fmaf(dv, w0[f], a0);
                    a1 = fmaf(dv, w0[9 + f], a1);
                    a2 = fmaf(dv, w0[18 + f], a2);
                    a3 = fmaf(dv, w0[27 + f], a3);
                }
                float4 hv = *(const float4*)(myh + 4 * q);   // conflict-free LDS.128
                float h0 = hv.x * __expf(-fmaxf(a0, 0.0f));
                float h1 = hv.y * __expf(-fmaxf(a1, 0.0f));
                float h2 = hv.z * __expf(-fmaxf(a2, 0.0f));
                float h3 = hv.w * __expf(-fmaxf(a3, 0.0f));
                hp[2 * q]     = pack2(h0, h1);
                hp[2 * q + 1] = pack2(h2, h3);
            }

            // ---- history regression x_h = h_dec @ W_hist^T + b (pairs) ----
            float xh[9];
            #pragma unroll
            for (int f = 0; f < 9; f++) {
                const float4* w = (const float4*)(s + OFF_WHIST + f * 64);
                float a0 = s[OFF_BHIST + f], a1 = 0.0f, a2 = 0.0f, a3 = 0.0f;
                #pragma unroll
                for (int q = 0; q < 16; q++) {
                    float4 wv = w[q];
                    float2 hA = unpack2(hp[2 * q]);
                    float2 hB = unpack2(hp[2 * q + 1]);
                    a0 = fmaf(hA.x, wv.x, a0);
                    a1 = fmaf(hA.y, wv.y, a1);
                    a2 = fmaf(hB.x, wv.z, a2);
                    a3 = fmaf(hB.y, wv.w, a3);
                }
                xh[f] = (a0 + a1) + (a2 + a3);
            }

            float xc[9], gx[9];
            #pragma unroll
            for (int f = 0; f < 9; f++) {
                xc[f] = m[f] * x[f] + (1.0f - m[f]) * xh[f];
                gx[f] = __expf(-fmaxf(fmaf(d[f], s[OFF_WGXD + f], s[OFF_BGX + f]), 0.0f));
            }

            float inp[18];
            float lsum = 0.0f;
            #pragma unroll
            for (int f = 0; f < 9; f++) {
                const float* wf = s + OFF_WFEAT + f * 9;
                float zh = s[OFF_BFEAT + f];
                #pragma unroll
                for (int k = 0; k < 9; k++) zh = fmaf(xc[k], wf[k], zh);
                const float* wc = s + OFF_WCOMB + f * 18;
                float al = s[OFF_BCOMB + f];
                #pragma unroll
                for (int k = 0; k < 9; k++) al = fmaf(gx[k], wc[k], al);
                #pragma unroll
                for (int k = 0; k < 9; k++) al = fmaf(m[k], wc[9 + k], al);
                float ch = al * zh + (1.0f - al) * xh[f];
                lsum += m[f] * (fabsf(x[f] - xh[f]) + fabsf(x[f] - zh) + fabsf(x[f] - ch));
                float c_c = m[f] * x[f] + (1.0f - m[f]) * ch;
                ob[t * 9 + f] = c_c;
                inp[f] = c_c;
                inp[9 + f] = m[f];
            }
            loss = fmaf(lsum, s[OFF_INV + t], loss);

            // pack inp into 9 k-pairs
            u64 inpp[9];
            #pragma unroll
            for (int kp = 0; kp < 9; kp++) inpp[kp] = pack2(inp[2 * kp], inp[2 * kp + 1]);

            // ---- LSTM gates: k-paired f32x2, 4 gate accumulators per unit ----
            #pragma unroll 1
            for (int j = 0; j < 64; j++) {
                const ulonglong2* wj = (const ulonglong2*)(s + OFF_WG + j * 328);
                const ulonglong2* bj = (const ulonglong2*)(s + OFF_B2 + j * 8);
                ulonglong2 b0 = bj[0], b1 = bj[1];
                u64 aI = b0.x, aF = b0.y, aG = b1.x, aO = b1.y;
                #pragma unroll
                for (int kp = 0; kp < 9; kp++) {
                    ulonglong2 w0 = wj[2 * kp];
                    ulonglong2 w1 = wj[2 * kp + 1];
                    u64 xv = inpp[kp];
                    fma2(aI, xv, w0.x);
                    fma2(aF, xv, w0.y);
                    fma2(aG, xv, w1.x);
                    fma2(aO, xv, w1.y);
                }
                #pragma unroll
                for (int kp = 0; kp < 32; kp++) {
                    ulonglong2 w0 = wj[18 + 2 * kp];
                    ulonglong2 w1 = wj[19 + 2 * kp];
                    u64 hv = hp[kp];
                    fma2(aI, hv, w0.x);
                    fma2(aF, hv, w0.y);
                    fma2(aG, hv, w1.x);
                    fma2(aO, hv, w1.y);
                }
                float2 vi = unpack2(aI), vf = unpack2(aF);
                float2 vg = unpack2(aG), vo = unpack2(aO);
                float gi = vi.x + vi.y, gf = vf.x + vf.y;
                float gg = vg.x + vg.y, go = vo.x + vo.y;
                float cn = fsigmoid(gf) * myc[j] + fsigmoid(gi) * ftanhx(gg);
                myc[j] = cn;
                myh[j] = fsigmoid(go) * ftanhx(cn);
            }
        }
    }

    // deterministic block reduction of loss
    #pragma unroll
    for (int o = 16; o; o >>= 1) loss += __shfl_down_sync(~0u, loss, o);
    __shared__ float red[4];
    if ((tid & 31) == 0) red[tid >> 5] = loss;
    __syncthreads();
    if (tid == 0) g_partials[blockIdx.x] = (red[0] + red[1]) + (red[2] + red[3]);
}

__global__ void finalize_kernel(float* __restrict__ out, int nblocks) {
    float sv = 0.0f;
    for (int i = threadIdx.x; i < nblocks; i += 256) sv += g_partials[i];
    __shared__ float red[8];
    #pragma unroll
    for (int o = 16; o; o >>= 1) sv += __shfl_down_sync(~0u, sv, o);
    if ((threadIdx.x & 31) == 0) red[threadIdx.x >> 5] = sv;
    __syncthreads();
    if (threadIdx.x < 8) {
        sv = red[threadIdx.x];
        #pragma unroll
        for (int o = 4; o; o >>= 1) sv += __shfl_down_sync(0xff, sv, o);
        if (threadIdx.x == 0) out[0] = sv * (1.0f / (float)TT);
    }
}

extern "C" void kernel_launch(void* const* d_in, const int* in_sizes, int n_in,
                              void* d_out, int out_size) {
    const float* values = (const float*)d_in[0];
    const float* masks  = (const float*)d_in[1];
    const float* deltas = (const float*)d_in[2];
    const float* Wgh   = (const float*)d_in[3];
    const float* bgh   = (const float*)d_in[4];
    const float* Wgx   = (const float*)d_in[5];
    const float* bgx   = (const float*)d_in[6];
    const float* Whist = (const float*)d_in[7];
    const float* bhist = (const float*)d_in[8];
    const float* Wfeat = (const float*)d_in[9];
    const float* bfeat = (const float*)d_in[10];
    const float* Wcomb = (const float*)d_in[11];
    const float* bcomb = (const float*)d_in[12];
    const float* Wih   = (const float*)d_in[13];
    const float* Whh   = (const float*)d_in[14];
    const float* bih   = (const float*)d_in[15];
    const float* bhh   = (const float*)d_in[16];
    float* out = (float*)d_out;

    int B = in_sizes[0] / (TT * FEAT);
    int nb = (B + BLK - 1) / BLK;

    cudaFuncSetAttribute(rits_main_kernel,
                         cudaFuncAttributeMaxDynamicSharedMemorySize, SMEM_BYTES);

    zero_denom_kernel<<<1, 64>>>();
    denom_kernel<<<(B * TT + 255) / 256, 256>>>(masks, B);
    rits_main_kernel<<<nb, BLK, SMEM_BYTES>>>(
        values, masks, deltas, Wgh, bgh, Wgx, bgx, Whist, bhist,
        Wfeat, bfeat, Wcomb, bcomb, Wih, Whh, bih, bhh, out, B);
    finalize_kernel<<<1, 256>>>(out, nb);
}

// round 8
// speedup vs baseline: 2.9417x; 1.0088x over previous
#include <cuda_runtime.h>
#include <cstdint>

#define HID  64
#define FEAT 9
#define TT   36
#define BLK  128

// ---- shared layout (float offsets) ----
#define OFF_WG     0         // [64][41 kpair][4 gate][2 parity] = 20992
#define OFF_B2     20992     // [64][4] u64 bias pairs (bias,0) = 512 floats
#define OFF_WGH    21504     // [64][9] = 576
#define OFF_BGH    22080     // 64
#define OFF_WHIST  22144     // [9][64] = 576
#define OFF_BHIST  22720     // 12
#define OFF_WGXD   22732     // 12
#define OFF_BGX    22744     // 12
#define OFF_WFEAT  22756     // 84
#define OFF_BFEAT  22840     // 12
#define OFF_WCOMB  22852     // 164
#define OFF_BCOMB  23016     // 12
#define OFF_INV    23028     // 36
#define OFF_H      23064     // [128][68]
#define OFF_C      (OFF_H + BLK*68)
#define SMEM_FLOATS (OFF_C + BLK*68)
#define SMEM_BYTES  (SMEM_FLOATS * 4)

__device__ float g_denom[TT];
__device__ float g_partials[1024];

typedef unsigned long long u64;

__device__ __forceinline__ void fma2(u64& acc, u64 a, u64 b) {
    asm("fma.rn.f32x2 %0, %1, %2, %0;" : "+l"(acc) : "l"(a), "l"(b));
}
__device__ __forceinline__ u64 pack2(float lo, float hi) {
    u64 r; asm("mov.b64 %0, {%1, %2};" : "=l"(r) : "f"(lo), "f"(hi)); return r;
}
__device__ __forceinline__ float2 unpack2(u64 v) {
    float2 r; asm("mov.b64 {%0, %1}, %2;" : "=f"(r.x), "=f"(r.y) : "l"(v)); return r;
}
__device__ __forceinline__ float fsigmoid(float x) {
    return __fdividef(1.0f, 1.0f + __expf(-x));
}
__device__ __forceinline__ float ftanhx(float x) {
    float e = __expf(2.0f * x);
    return 1.0f - __fdividef(2.0f, e + 1.0f);
}

// ---- denom: zero bins, then coalesced accumulate (exact-integer atomics) ----
__global__ void zero_denom_kernel() {
    if (threadIdx.x < TT) g_denom[threadIdx.x] = 0.0f;
}
__global__ void denom_kernel(const float* __restrict__ masks, int B) {
    __shared__ float bins[TT];
    if (threadIdx.x < TT) bins[threadIdx.x] = 0.0f;
    __syncthreads();
    int idx = blockIdx.x * blockDim.x + threadIdx.x;
    if (idx < B * TT) {
        int t = idx % TT;
        const float* p = masks + (size_t)idx * FEAT;
        float sv = 0.0f;
        #pragma unroll
        for (int f = 0; f < FEAT; f++) sv += p[f];
        atomicAdd(&bins[t], sv);
    }
    __syncthreads();
    if (threadIdx.x < TT) atomicAdd(&g_denom[threadIdx.x], bins[threadIdx.x]);
}

__global__ void __launch_bounds__(BLK)
rits_main_kernel(const float* __restrict__ values,
                 const float* __restrict__ masks,
                 const float* __restrict__ deltas,
                 const float* __restrict__ Wgh, const float* __restrict__ bgh,
                 const float* __restrict__ Wgx, const float* __restrict__ bgx,
                 const float* __restrict__ Whist, const float* __restrict__ bhist,
                 const float* __restrict__ Wfeat, const float* __restrict__ bfeat,
                 const float* __restrict__ Wcomb, const float* __restrict__ bcomb,
                 const float* __restrict__ Wih, const float* __restrict__ Whh,
                 const float* __restrict__ bih, const float* __restrict__ bhh,
                 float* __restrict__ out, int B) {
    extern __shared__ float s[];
    const int tid = threadIdx.x;
    const int b = blockIdx.x * BLK + tid;

    // ---- stage gate weights: [j][kp][gate][parity], k = 2*kp+parity ----
    for (int idx = tid; idx < 64 * 328; idx += BLK) {
        int j = idx / 328, r = idx - j * 328;
        int kp = r >> 3, g = (r & 7) >> 1, p = r & 1;
        int k = 2 * kp + p;
        int row = g * HID + j;
        s[OFF_WG + idx] = (k < 18) ? Wih[row * 18 + k] : Whh[row * HID + (k - 18)];
    }
    // bias pairs (bias, 0) per [j][gate]
    for (int idx = tid; idx < 256; idx += BLK) {
        int j = idx >> 2, g = idx & 3;
        s[OFF_B2 + idx * 2]     = bih[g * HID + j] + bhh[g * HID + j];
        s[OFF_B2 + idx * 2 + 1] = 0.0f;
    }
    for (int idx = tid; idx < 576; idx += BLK) {
        s[OFF_WGH + idx] = Wgh[idx];
        s[OFF_WHIST + idx] = Whist[idx];
    }
    for (int idx = tid; idx < 164; idx += BLK)
        s[OFF_WCOMB + idx] = (idx < 162) ? Wcomb[idx] : 0.0f;
    if (tid < 64) s[OFF_BGH + tid] = bgh[tid];
    if (tid < 12) {
        s[OFF_BHIST + tid] = (tid < 9) ? bhist[tid] : 0.0f;
        s[OFF_WGXD + tid]  = (tid < 9) ? Wgx[tid * FEAT + tid] : 0.0f;
        s[OFF_BGX + tid]   = (tid < 9) ? bgx[tid] : 0.0f;
        s[OFF_BFEAT + tid] = (tid < 9) ? bfeat[tid] : 0.0f;
        s[OFF_BCOMB + tid] = (tid < 9) ? bcomb[tid] : 0.0f;
    }
    if (tid < 84) {
        int f = tid / 9, f2 = tid - f * 9;
        s[OFF_WFEAT + tid] = (tid < 81 && f != f2) ? Wfeat[tid] : 0.0f;
    }
    if (tid < TT) s[OFF_INV + tid] = 1.0f / (g_denom[tid] + 1e-5f);

    float* myh = s + OFF_H + tid * 68;
    float* myc = s + OFF_C + tid * 68;
    #pragma unroll
    for (int k = 0; k < 68; k++) { myh[k] = 0.0f; myc[k] = 0.0f; }
    __syncthreads();

    float loss = 0.0f;
    if (b < B) {
        const float* xb = values + (size_t)b * (TT * FEAT);
        const float* mb = masks + (size_t)b * (TT * FEAT);
        const float* db = deltas + (size_t)b * (TT * FEAT);
        float* ob = out + 1 + (size_t)b * (TT * FEAT);

        for (int t = 0; t < TT; t++) {
            float x[9], m[9], d[9];
            #pragma unroll
            for (int f = 0; f < 9; f++) {
                x[f] = xb[t * 9 + f];
                m[f] = mb[t * 9 + f];
                d[f] = db[t * 9 + f];
            }

            // ---- decay + hoist: hp[32] = packed pairs of decayed h ----
            u64 hp[32];
            #pragma unroll 4
            for (int q = 0; q < 16; q++) {
                const float* w0 = s + OFF_WGH + (4 * q) * 9;
                float a0 = s[OFF_BGH + 4 * q];
                float a1 = s[OFF_BGH + 4 * q + 1];
                float a2 = s[OFF_BGH + 4 * q + 2];
                float a3 = s[OFF_BGH + 4 * q + 3];
                #pragma unroll
                for (int f = 0; f < 9; f++) {
                    float dv = d[f];
                    a0 = fmaf(dv, w0[f], a0);
                    a1 = fmaf(dv, w0[9 + f], a1);
                    a2 = fmaf(dv, w0[18 + f], a2);
                    a3 = fmaf(dv, w0[27 + f], a3);
                }
                float4 hv = *(const float4*)(myh + 4 * q);   // conflict-free LDS.128
                float h0 = hv.x * __expf(-fmaxf(a0, 0.0f));
                float h1 = hv.y * __expf(-fmaxf(a1, 0.0f));
                float h2 = hv.z * __expf(-fmaxf(a2, 0.0f));
                float h3 = hv.w * __expf(-fmaxf(a3, 0.0f));
                hp[2 * q]     = pack2(h0, h1);
                hp[2 * q + 1] = pack2(h2, h3);
            }

            // ---- history regression x_h = h_dec @ W_hist^T + b (pairs) ----
            float xh[9];
            #pragma unroll
            for (int f = 0; f < 9; f++) {
                const float4* w = (const float4*)(s + OFF_WHIST + f * 64);
                float a0 = s[OFF_BHIST + f], a1 = 0.0f, a2 = 0.0f, a3 = 0.0f;
                #pragma unroll
                for (int q = 0; q < 16; q++) {
                    float4 wv = w[q];
                    float2 hA = unpack2(hp[2 * q]);
                    float2 hB = unpack2(hp[2 * q + 1]);
                    a0 = fmaf(hA.x, wv.x, a0);
                    a1 = fmaf(hA.y, wv.y, a1);
                    a2 = fmaf(hB.x, wv.z, a2);
                    a3 = fmaf(hB.y, wv.w, a3);
                }
                xh[f] = (a0 + a1) + (a2 + a3);
            }

            float xc[9], gx[9];
            #pragma unroll
            for (int f = 0; f < 9; f++) {
                xc[f] = m[f] * x[f] + (1.0f - m[f]) * xh[f];
                gx[f] = __expf(-fmaxf(fmaf(d[f], s[OFF_WGXD + f], s[OFF_BGX + f]), 0.0f));
            }

            float inp[18];
            float lsum = 0.0f;
            #pragma unroll
            for (int f = 0; f < 9; f++) {
                const float* wf = s + OFF_WFEAT + f * 9;
                float zh = s[OFF_BFEAT + f];
                #pragma unroll
                for (int k = 0; k < 9; k++) zh = fmaf(xc[k], wf[k], zh);
                const float* wc = s + OFF_WCOMB + f * 18;
                float al = s[OFF_BCOMB + f];
                #pragma unroll
                for (int k = 0; k < 9; k++) al = fmaf(gx[k], wc[k], al);
                #pragma unroll
                for (int k = 0; k < 9; k++) al = fmaf(m[k], wc[9 + k], al);
                float ch = al * zh + (1.0f - al) * xh[f];
                lsum += m[f] * (fabsf(x[f] - xh[f]) + fabsf(x[f] - zh) + fabsf(x[f] - ch));
                float c_c = m[f] * x[f] + (1.0f - m[f]) * ch;
                ob[t * 9 + f] = c_c;
                inp[f] = c_c;
                inp[9 + f] = m[f];
            }
            loss = fmaf(lsum, s[OFF_INV + t], loss);

            // pack inp into 9 k-pairs
            u64 inpp[9];
            #pragma unroll
            for (int kp = 0; kp < 9; kp++) inpp[kp] = pack2(inp[2 * kp], inp[2 * kp + 1]);

            // ---- LSTM gates: 2 units per iteration -> 8 independent FFMA2 chains ----
            #pragma unroll 1
            for (int jg = 0; jg < 32; jg++) {
                const int j0 = 2 * jg;
                const ulonglong2* wA = (const ulonglong2*)(s + OFF_WG + j0 * 328);
                const ulonglong2* wB = (const ulonglong2*)(s + OFF_WG + (j0 + 1) * 328);
                const ulonglong2* bA = (const ulonglong2*)(s + OFF_B2 + j0 * 8);
                ulonglong2 bA0 = bA[0], bA1 = bA[1], bB0 = bA[2], bB1 = bA[3];
                u64 aI0 = bA0.x, aF0 = bA0.y, aG0 = bA1.x, aO0 = bA1.y;
                u64 aI1 = bB0.x, aF1 = bB0.y, aG1 = bB1.x, aO1 = bB1.y;
                #pragma unroll
                for (int kp = 0; kp < 9; kp++) {
                    ulonglong2 wa0 = wA[2 * kp];
                    ulonglong2 wa1 = wA[2 * kp + 1];
                    ulonglong2 wb0 = wB[2 * kp];
                    ulonglong2 wb1 = wB[2 * kp + 1];
                    u64 xv = inpp[kp];
                    fma2(aI0, xv, wa0.x);
                    fma2(aF0, xv, wa0.y);
                    fma2(aI1, xv, wb0.x);
                    fma2(aF1, xv, wb0.y);
                    fma2(aG0, xv, wa1.x);
                    fma2(aO0, xv, wa1.y);
                    fma2(aG1, xv, wb1.x);
                    fma2(aO1, xv, wb1.y);
                }
                #pragma unroll
                for (int kp = 0; kp < 32; kp++) {
                    ulonglong2 wa0 = wA[18 + 2 * kp];
                    ulonglong2 wa1 = wA[19 + 2 * kp];
                    ulonglong2 wb0 = wB[18 + 2 * kp];
                    ulonglong2 wb1 = wB[19 + 2 * kp];
                    u64 hv = hp[kp];
                    fma2(aI0, hv, wa0.x);
                    fma2(aF0, hv, wa0.y);
                    fma2(aI1, hv, wb0.x);
                    fma2(aF1, hv, wb0.y);
                    fma2(aG0, hv, wa1.x);
                    fma2(aO0, hv, wa1.y);
                    fma2(aG1, hv, wb1.x);
                    fma2(aO1, hv, wb1.y);
                }
                // epilogue for both units; c via conflict-free float2
                float2 cc = *(const float2*)(myc + j0);
                float2 vi0 = unpack2(aI0), vf0 = unpack2(aF0);
                float2 vg0 = unpack2(aG0), vo0 = unpack2(aO0);
                float2 vi1 = unpack2(aI1), vf1 = unpack2(aF1);
                float2 vg1 = unpack2(aG1), vo1 = unpack2(aO1);
                float gi0 = vi0.x + vi0.y, gf0 = vf0.x + vf0.y;
                float gg0 = vg0.x + vg0.y, go0 = vo0.x + vo0.y;
                float gi1 = vi1.x + vi1.y, gf1 = vf1.x + vf1.y;
                float gg1 = vg1.x + vg1.y, go1 = vo1.x + vo1.y;
                float cn0 = fsigmoid(gf0) * cc.x + fsigmoid(gi0) * ftanhx(gg0);
                float cn1 = fsigmoid(gf1) * cc.y + fsigmoid(gi1) * ftanhx(gg1);
                *(float2*)(myc + j0) = make_float2(cn0, cn1);
                float h0 = fsigmoid(go0) * ftanhx(cn0);
                float h1 = fsigmoid(go1) * ftanhx(cn1);
                *(float2*)(myh + j0) = make_float2(h0, h1);
            }
        }
    }

    // deterministic block reduction of loss
    #pragma unroll
    for (int o = 16; o; o >>= 1) loss += __shfl_down_sync(~0u, loss, o);
    __shared__ float red[4];
    if ((tid & 31) == 0) red[tid >> 5] = loss;
    __syncthreads();
    if (tid == 0) g_partials[blockIdx.x] = (red[0] + red[1]) + (red[2] + red[3]);
}

__global__ void finalize_kernel(float* __restrict__ out, int nblocks) {
    float sv = 0.0f;
    for (int i = threadIdx.x; i < nblocks; i += 256) sv += g_partials[i];
    __shared__ float red[8];
    #pragma unroll
    for (int o = 16; o; o >>= 1) sv += __shfl_down_sync(~0u, sv, o);
    if ((threadIdx.x & 31) == 0) red[threadIdx.x >> 5] = sv;
    __syncthreads();
    if (threadIdx.x < 8) {
        sv = red[threadIdx.x];
        #pragma unroll
        for (int o = 4; o; o >>= 1) sv += __shfl_down_sync(0xff, sv, o);
        if (threadIdx.x == 0) out[0] = sv * (1.0f / (float)TT);
    }
}

extern "C" void kernel_launch(void* const* d_in, const int* in_sizes, int n_in,
                              void* d_out, int out_size) {
    const float* values = (const float*)d_in[0];
    const float* masks  = (const float*)d_in[1];
    const float* deltas = (const float*)d_in[2];
    const float* Wgh   = (const float*)d_in[3];
    const float* bgh   = (const float*)d_in[4];
    const float* Wgx   = (const float*)d_in[5];
    const float* bgx   = (const float*)d_in[6];
    const float* Whist = (const float*)d_in[7];
    const float* bhist = (const float*)d_in[8];
    const float* Wfeat = (const float*)d_in[9];
    const float* bfeat = (const float*)d_in[10];
    const float* Wcomb = (const float*)d_in[11];
    const float* bcomb = (const float*)d_in[12];
    const float* Wih   = (const float*)d_in[13];
    const float* Whh   = (const float*)d_in[14];
    const float* bih   = (const float*)d_in[15];
    const float* bhh   = (const float*)d_in[16];
    float* out = (float*)d_out;

    int B = in_sizes[0] / (TT * FEAT);
    int nb = (B + BLK - 1) / BLK;

    cudaFuncSetAttribute(rits_main_kernel,
                         cudaFuncAttributeMaxDynamicSharedMemorySize, SMEM_BYTES);

    zero_denom_kernel<<<1, 64>>>();
    denom_kernel<<<(B * TT + 255) / 256, 256>>>(masks, B);
    rits_main_kernel<<<nb, BLK, SMEM_BYTES>>>(
        values, masks, deltas, Wgh, bgh, Wgx, bgx, Whist, bhist,
        Wfeat, bfeat, Wcomb, bcomb, Wih, Whh, bih, bhh, out, B);
    finalize_kernel<<<1, 256>>>(out, nb);
}

// round 9
// speedup vs baseline: 2.9513x; 1.0032x over previous
#include <cuda_runtime.h>
#include <cstdint>

#define HID  64
#define FEAT 9
#define TT   36
#define BLK  256
#define BPB  128   // batch elements per block

// ---- shared layout (float offsets) ----
#define OFF_WG     0         // [64][41 kpair][4 gate][2 parity] = 20992
#define OFF_B2     20992     // [64][4] pairs (bias,0) = 512 floats
#define OFF_WGH    21504     // [64][9] = 576
#define OFF_BGH    22080     // 64
#define OFF_WHIST  22144     // [9][64] = 576
#define OFF_BHIST  22720     // 12
#define OFF_WGXD   22732     // 12
#define OFF_BGX    22744     // 12
#define OFF_WFEAT  22756     // 84
#define OFF_BFEAT  22840     // 12
#define OFF_WCOMB  22852     // 164
#define OFF_BCOMB  23016     // 12
#define OFF_INV    23028     // 36
#define OFF_H      23064     // [128][68]
#define OFF_C      (OFF_H + BPB*68)
#define SMEM_FLOATS (OFF_C + BPB*68)
#define SMEM_BYTES  (SMEM_FLOATS * 4)

__device__ float g_denom[TT];
__device__ float g_partials[1024];

typedef unsigned long long u64;

__device__ __forceinline__ void fma2(u64& acc, u64 a, u64 b) {
    asm("fma.rn.f32x2 %0, %1, %2, %0;" : "+l"(acc) : "l"(a), "l"(b));
}
__device__ __forceinline__ u64 pack2(float lo, float hi) {
    u64 r; asm("mov.b64 %0, {%1, %2};" : "=l"(r) : "f"(lo), "f"(hi)); return r;
}
__device__ __forceinline__ float2 unpack2(u64 v) {
    float2 r; asm("mov.b64 {%0, %1}, %2;" : "=f"(r.x), "=f"(r.y) : "l"(v)); return r;
}
__device__ __forceinline__ float fsigmoid(float x) {
    return __fdividef(1.0f, 1.0f + __expf(-x));
}
__device__ __forceinline__ float ftanhx(float x) {
    float e = __expf(2.0f * x);
    return 1.0f - __fdividef(2.0f, e + 1.0f);
}

// ---- denom: zero bins, then coalesced accumulate (exact-integer atomics) ----
__global__ void zero_denom_kernel() {
    if (threadIdx.x < TT) g_denom[threadIdx.x] = 0.0f;
}
__global__ void denom_kernel(const float* __restrict__ masks, int B) {
    __shared__ float bins[TT];
    if (threadIdx.x < TT) bins[threadIdx.x] = 0.0f;
    __syncthreads();
    int idx = blockIdx.x * blockDim.x + threadIdx.x;
    if (idx < B * TT) {
        int t = idx % TT;
        const float* p = masks + (size_t)idx * FEAT;
        float sv = 0.0f;
        #pragma unroll
        for (int f = 0; f < FEAT; f++) sv += p[f];
        atomicAdd(&bins[t], sv);
    }
    __syncthreads();
    if (threadIdx.x < TT) atomicAdd(&g_denom[threadIdx.x], bins[threadIdx.x]);
}

__global__ void __launch_bounds__(BLK)
rits_main_kernel(const float* __restrict__ values,
                 const float* __restrict__ masks,
                 const float* __restrict__ deltas,
                 const float* __restrict__ Wgh, const float* __restrict__ bgh,
                 const float* __restrict__ Wgx, const float* __restrict__ bgx,
                 const float* __restrict__ Whist, const float* __restrict__ bhist,
                 const float* __restrict__ Wfeat, const float* __restrict__ bfeat,
                 const float* __restrict__ Wcomb, const float* __restrict__ bcomb,
                 const float* __restrict__ Wih, const float* __restrict__ Whh,
                 const float* __restrict__ bih, const float* __restrict__ bhh,
                 float* __restrict__ out, int B) {
    extern __shared__ float s[];
    const int tid = threadIdx.x;
    const int lane = tid & (BPB - 1);   // batch lane within block
    const int role = tid >> 7;          // 0: units 0-31, 1: units 32-63
    const int jbase = role << 5;
    const int qbase = role << 3;
    const int b = blockIdx.x * BPB + lane;

    // ---- stage gate weights: [j][kp][gate][parity], k = 2*kp+parity ----
    for (int idx = tid; idx < 64 * 328; idx += BLK) {
        int j = idx / 328, r = idx - j * 328;
        int kp = r >> 3, g = (r & 7) >> 1, p = r & 1;
        int k = 2 * kp + p;
        int row = g * HID + j;
        s[OFF_WG + idx] = (k < 18) ? Wih[row * 18 + k] : Whh[row * HID + (k - 18)];
    }
    if (tid < 256) {
        int j = tid >> 2, g = tid & 3;
        s[OFF_B2 + tid * 2]     = bih[g * HID + j] + bhh[g * HID + j];
        s[OFF_B2 + tid * 2 + 1] = 0.0f;
    }
    for (int idx = tid; idx < 576; idx += BLK) {
        s[OFF_WGH + idx] = Wgh[idx];
        s[OFF_WHIST + idx] = Whist[idx];
    }
    if (tid < 164) s[OFF_WCOMB + tid] = (tid < 162) ? Wcomb[tid] : 0.0f;
    if (tid < 64) s[OFF_BGH + tid] = bgh[tid];
    if (tid < 12) {
        s[OFF_BHIST + tid] = (tid < 9) ? bhist[tid] : 0.0f;
        s[OFF_WGXD + tid]  = (tid < 9) ? Wgx[tid * FEAT + tid] : 0.0f;
        s[OFF_BGX + tid]   = (tid < 9) ? bgx[tid] : 0.0f;
        s[OFF_BFEAT + tid] = (tid < 9) ? bfeat[tid] : 0.0f;
        s[OFF_BCOMB + tid] = (tid < 9) ? bcomb[tid] : 0.0f;
    }
    if (tid < 84) {
        int f = tid / 9, f2 = tid - f * 9;
        s[OFF_WFEAT + tid] = (tid < 81 && f != f2) ? Wfeat[tid] : 0.0f;
    }
    if (tid < TT) s[OFF_INV + tid] = 1.0f / (g_denom[tid] + 1e-5f);

    float* myh = s + OFF_H + lane * 68;
    float* myc = s + OFF_C + lane * 68;
    if (role == 0) {
        #pragma unroll
        for (int k = 0; k < 68; k++) { myh[k] = 0.0f; myc[k] = 0.0f; }
    }
    __syncthreads();

    const int bb = (b < B) ? b : (B - 1);
    const bool active = (b < B);
    const float* xb = values + (size_t)bb * (TT * FEAT);
    const float* mb = masks + (size_t)bb * (TT * FEAT);
    const float* db = deltas + (size_t)bb * (TT * FEAT);
    float* ob = out + 1 + (size_t)bb * (TT * FEAT);

    float loss = 0.0f;
    for (int t = 0; t < TT; t++) {
        float x[9], m[9], d[9];
        #pragma unroll
        for (int f = 0; f < 9; f++) {
            x[f] = xb[t * 9 + f];
            m[f] = mb[t * 9 + f];
            d[f] = db[t * 9 + f];
        }

        // ---- phase A: decay OWN 32 units, in place in shared ----
        #pragma unroll
        for (int q8 = 0; q8 < 8; q8++) {
            const int q = qbase + q8;
            const float* w0 = s + OFF_WGH + (4 * q) * 9;
            float a0 = s[OFF_BGH + 4 * q];
            float a1 = s[OFF_BGH + 4 * q + 1];
            float a2 = s[OFF_BGH + 4 * q + 2];
            float a3 = s[OFF_BGH + 4 * q + 3];
            #pragma unroll
            for (int f = 0; f < 9; f++) {
                float dv = d[f];
                a0 = fmaf(dv, w0[f], a0);
                a1 = fmaf(dv, w0[9 + f], a1);
                a2 = fmaf(dv, w0[18 + f], a2);
                a3 = fmaf(dv, w0[27 + f], a3);
            }
            float4 hv = *(const float4*)(myh + 4 * q);
            hv.x *= __expf(-fmaxf(a0, 0.0f));
            hv.y *= __expf(-fmaxf(a1, 0.0f));
            hv.z *= __expf(-fmaxf(a2, 0.0f));
            hv.w *= __expf(-fmaxf(a3, 0.0f));
            *(float4*)(myh + 4 * q) = hv;
        }
        __syncthreads();

        // ---- B1: both roles load the FULL decayed h as pairs ----
        u64 hp[32];
        #pragma unroll
        for (int k = 0; k < 16; k++) {
            float4 v = *(const float4*)(myh + 4 * k);
            hp[2 * k]     = pack2(v.x, v.y);
            hp[2 * k + 1] = pack2(v.z, v.w);
        }
        __syncthreads();   // all reads done before any role writes new h

        // ---- B2: regressions (duplicated across roles; identical) ----
        float xh[9];
        #pragma unroll
        for (int f = 0; f < 9; f++) {
            const float4* w = (const float4*)(s + OFF_WHIST + f * 64);
            float a0 = s[OFF_BHIST + f], a1 = 0.0f, a2 = 0.0f, a3 = 0.0f;
            #pragma unroll
            for (int q = 0; q < 16; q++) {
                float4 wv = w[q];
                float2 hA = unpack2(hp[2 * q]);
                float2 hB = unpack2(hp[2 * q + 1]);
                a0 = fmaf(hA.x, wv.x, a0);
                a1 = fmaf(hA.y, wv.y, a1);
                a2 = fmaf(hB.x, wv.z, a2);
                a3 = fmaf(hB.y, wv.w, a3);
            }
            xh[f] = (a0 + a1) + (a2 + a3);
        }

        float xc[9], gx[9];
        #pragma unroll
        for (int f = 0; f < 9; f++) {
            xc[f] = m[f] * x[f] + (1.0f - m[f]) * xh[f];
            gx[f] = __expf(-fmaxf(fmaf(d[f], s[OFF_WGXD + f], s[OFF_BGX + f]), 0.0f));
        }

        float inp[18];
        float lsum = 0.0f;
        #pragma unroll
        for (int f = 0; f < 9; f++) {
            const float* wf = s + OFF_WFEAT + f * 9;
            float zh = s[OFF_BFEAT + f];
            #pragma unroll
            for (int k = 0; k < 9; k++) zh = fmaf(xc[k], wf[k], zh);
            const float* wc = s + OFF_WCOMB + f * 18;
            float al = s[OFF_BCOMB + f];
            #pragma unroll
            for (int k = 0; k < 9; k++) al = fmaf(gx[k], wc[k], al);
            #pragma unroll
            for (int k = 0; k < 9; k++) al = fmaf(m[k], wc[9 + k], al);
            float ch = al * zh + (1.0f - al) * xh[f];
            lsum += m[f] * (fabsf(x[f] - xh[f]) + fabsf(x[f] - zh) + fabsf(x[f] - ch));
            float c_c = m[f] * x[f] + (1.0f - m[f]) * ch;
            if (active && role == 0) ob[t * 9 + f] = c_c;
            inp[f] = c_c;
            inp[9 + f] = m[f];
        }
        if (active && role == 0) loss = fmaf(lsum, s[OFF_INV + t], loss);

        u64 inpp[9];
        #pragma unroll
        for (int kp = 0; kp < 9; kp++) inpp[kp] = pack2(inp[2 * kp], inp[2 * kp + 1]);

        // ---- gates for OWN 32 units (k-paired f32x2, 4 chains) ----
        #pragma unroll 1
        for (int jj = 0; jj < 32; jj++) {
            const int j = jbase + jj;
            const ulonglong2* wj = (const ulonglong2*)(s + OFF_WG + j * 328);
            const ulonglong2* bj = (const ulonglong2*)(s + OFF_B2 + j * 8);
            ulonglong2 b0 = bj[0], b1 = bj[1];
            u64 aI = b0.x, aF = b0.y, aG = b1.x, aO = b1.y;
            #pragma unroll
            for (int kp = 0; kp < 9; kp++) {
                ulonglong2 w0 = wj[2 * kp];
                ulonglong2 w1 = wj[2 * kp + 1];
                u64 xv = inpp[kp];
                fma2(aI, xv, w0.x);
                fma2(aF, xv, w0.y);
                fma2(aG, xv, w1.x);
                fma2(aO, xv, w1.y);
            }
            #pragma unroll
            for (int kp = 0; kp < 32; kp++) {
                ulonglong2 w0 = wj[18 + 2 * kp];
                ulonglong2 w1 = wj[19 + 2 * kp];
                u64 hv = hp[kp];
                fma2(aI, hv, w0.x);
                fma2(aF, hv, w0.y);
                fma2(aG, hv, w1.x);
                fma2(aO, hv, w1.y);
            }
            float2 vi = unpack2(aI), vf = unpack2(aF);
            float2 vg = unpack2(aG), vo = unpack2(aO);
            float gi = vi.x + vi.y, gf = vf.x + vf.y;
            float gg = vg.x + vg.y, go = vo.x + vo.y;
            float cn = fsigmoid(gf) * myc[j] + fsigmoid(gi) * ftanhx(gg);
            myc[j] = cn;
            myh[j] = fsigmoid(go) * ftanhx(cn);
        }
        // no sync needed here: next phase A touches only own units
    }

    // deterministic block reduction of loss (role 1 contributes zeros)
    #pragma unroll
    for (int o = 16; o; o >>= 1) loss += __shfl_down_sync(~0u, loss, o);
    __shared__ float red[8];
    if ((tid & 31) == 0) red[tid >> 5] = loss;
    __syncthreads();
    if (tid == 0) {
        float sv = ((red[0] + red[1]) + (red[2] + red[3]))
                 + ((red[4] + red[5]) + (red[6] + red[7]));
        g_partials[blockIdx.x] = sv;
    }
}

__global__ void finalize_kernel(float* __restrict__ out, int nblocks) {
    float sv = 0.0f;
    for (int i = threadIdx.x; i < nblocks; i += 256) sv += g_partials[i];
    __shared__ float red[8];
    #pragma unroll
    for (int o = 16; o; o >>= 1) sv += __shfl_down_sync(~0u, sv, o);
    if ((threadIdx.x & 31) == 0) red[threadIdx.x >> 5] = sv;
    __syncthreads();
    if (threadIdx.x < 8) {
        sv = red[threadIdx.x];
        #pragma unroll
        for (int o = 4; o; o >>= 1) sv += __shfl_down_sync(0xff, sv, o);
        if (threadIdx.x == 0) out[0] = sv * (1.0f / (float)TT);
    }
}

extern "C" void kernel_launch(void* const* d_in, const int* in_sizes, int n_in,
                              void* d_out, int out_size) {
    const float* values = (const float*)d_in[0];
    const float* masks  = (const float*)d_in[1];
    const float* deltas = (const float*)d_in[2];
    const float* Wgh   = (const float*)d_in[3];
    const float* bgh   = (const float*)d_in[4];
    const float* Wgx   = (const float*)d_in[5];
    const float* bgx   = (const float*)d_in[6];
    const float* Whist = (const float*)d_in[7];
    const float* bhist = (const float*)d_in[8];
    const float* Wfeat = (const float*)d_in[9];
    const float* bfeat = (const float*)d_in[10];
    const float* Wcomb = (const float*)d_in[11];
    const float* bcomb = (const float*)d_in[12];
    const float* Wih   = (const float*)d_in[13];
    const float* Whh   = (const float*)d_in[14];
    const float* bih   = (const float*)d_in[15];
    const float* bhh   = (const float*)d_in[16];
    float* out = (float*)d_out;

    int B = in_sizes[0] / (TT * FEAT);
    int nb = (B + BPB - 1) / BPB;

    cudaFuncSetAttribute(rits_main_kernel,
                         cudaFuncAttributeMaxDynamicSharedMemorySize, SMEM_BYTES);

    zero_denom_kernel<<<1, 64>>>();
    denom_kernel<<<(B * TT + 255) / 256, 256>>>(masks, B);
    rits_main_kernel<<<nb, BLK, SMEM_BYTES>>>(
        values, masks, deltas, Wgh, bgh, Wgx, bgx, Whist, bhist,
        Wfeat, bfeat, Wcomb, bcomb, Wih, Whh, bih, bhh, out, B);
    finalize_kernel<<<1, 256>>>(out, nb);
}